// round 5
// baseline (speedup 1.0000x reference)
#include <cuda_runtime.h>
#include <cstdint>

#define Bb   4
#define Hh   176
#define Ww   200
#define CIN  128
#define COUT 256
#define NPTS (4096*64)
#define NCELL (Bb*Ww*Hh)
#define EPSf 1e-5f

#define TILE_M 64           // cells per GEMM tile

// -------- scratch (device globals; no allocation allowed) --------
__device__ float g_dense[(size_t)NCELL*CIN];        // 72 MB scatter target
__device__ int   g_cnt[NCELL];                      // points per cell
__device__ int   g_start[NCELL];                    // CSR segment base
__device__ int   g_fill[NCELL];                     // CSR fill cursor
__device__ int   g_pts[NPTS];                       // CSR point ids
__device__ int   g_celllist[NCELL];
__device__ int   g_ncells;
__device__ int   g_nptstotal;
__device__ float g_W2[COUT*CIN];                    // W*gamma (full fp32), [o][c]
__device__ float g_gw[COUT];                        // sum_c W2[o,c]
__device__ float g_bias2[COUT];                     // sum_c beta[c]*W[o,c]

// ======================= helpers =======================
__device__ __forceinline__ float to_tf32(float x) {
    float y; asm("cvt.rna.tf32.f32 %0, %1;" : "=f"(y) : "f"(x)); return y;
}

__device__ __forceinline__ void mma8(float* c, const uint32_t* a, const uint32_t* b) {
    asm volatile(
        "mma.sync.aligned.m16n8k8.row.col.f32.tf32.tf32.f32 "
        "{%0,%1,%2,%3}, {%4,%5,%6,%7}, {%8,%9}, {%0,%1,%2,%3};"
        : "+f"(c[0]), "+f"(c[1]), "+f"(c[2]), "+f"(c[3])
        : "r"(a[0]), "r"(a[1]), "r"(a[2]), "r"(a[3]), "r"(b[0]), "r"(b[1]));
}

// swizzled element index (floats) in a row-major [rows][128] tile
__device__ __forceinline__ int swidx(int r, int f4, int w) {
    return (r * 32 + (f4 ^ (r & 7))) * 4 + w;
}

// ======================= small kernels =======================
__global__ void k_zero() {
    int i = blockIdx.x * blockDim.x + threadIdx.x;
    int stride = gridDim.x * blockDim.x;
    float4 z = make_float4(0.f, 0.f, 0.f, 0.f);
    float4* d4 = (float4*)g_dense;
    const int n4 = NCELL * CIN / 4;
    for (int j = i; j < n4; j += stride) d4[j] = z;
    for (int j = i; j < NCELL; j += stride) g_cnt[j] = 0;
    if (i == 0) { g_ncells = 0; g_nptstotal = 0; }
}

__global__ void k_prep(const float* __restrict__ lw,
                       const float* __restrict__ gamma,
                       const float* __restrict__ beta) {
    int o = blockIdx.x;
    int c = threadIdx.x;
    float w  = lw[o * CIN + c];
    float w2 = w * gamma[c];
    g_W2[o * CIN + c] = w2;
    float gwv = w2;
    float b2  = w * beta[c];
    for (int s = 16; s > 0; s >>= 1) {
        gwv += __shfl_xor_sync(0xFFFFFFFFu, gwv, s);
        b2  += __shfl_xor_sync(0xFFFFFFFFu, b2,  s);
    }
    __shared__ float sg[4], sb[4];
    if ((c & 31) == 0) { sg[c >> 5] = gwv; sb[c >> 5] = b2; }
    __syncthreads();
    if (c == 0) {
        g_gw[o]    = sg[0] + sg[1] + sg[2] + sg[3];
        g_bias2[o] = sb[0] + sb[1] + sb[2] + sb[3];
    }
}

// scatter-add (1 warp/point, red.v4); invalid points zero their output row here
__global__ void k_scatter(const float* __restrict__ feats,
                          const int* __restrict__ idx,
                          float* __restrict__ out) {
    int g = blockIdx.x * blockDim.x + threadIdx.x;
    int p = g >> 5;
    int l = g & 31;
    if (p >= NPTS) return;
    int b = idx[3 * p + 0];
    int x = idx[3 * p + 1];
    int y = idx[3 * p + 2];
    if ((unsigned)x >= (unsigned)Hh || (unsigned)y >= (unsigned)Ww) {
        float4 z = make_float4(0.f, 0.f, 0.f, 0.f);
        float4* o4 = (float4*)(out + (size_t)p * COUT);
        o4[2 * l]     = z;
        o4[2 * l + 1] = z;
        return;
    }
    int cell = (b * Ww + y) * Hh + x;
    float4 v = ((const float4*)(feats + (size_t)p * CIN))[l];
    float* dst = g_dense + (size_t)cell * CIN + 4 * l;
    asm volatile("red.global.add.v4.f32 [%0], {%1, %2, %3, %4};"
                 :: "l"(dst), "f"(v.x), "f"(v.y), "f"(v.z), "f"(v.w) : "memory");
    if (l == 0) atomicAdd(&g_cnt[cell], 1);
}

// compact occupied cells + assign CSR segments
__global__ void k_compact() {
    int c = blockIdx.x * blockDim.x + threadIdx.x;
    if (c < NCELL) {
        int cnt = g_cnt[c];
        if (cnt > 0) {
            int pos = atomicAdd(&g_ncells, 1);
            g_celllist[pos] = c;
            int base = atomicAdd(&g_nptstotal, cnt);
            g_start[c] = base;
            g_fill[c]  = base;
        }
    }
}

// CSR fill: record which points own each cell
__global__ void k_fill(const int* __restrict__ idx) {
    int p = blockIdx.x * blockDim.x + threadIdx.x;
    if (p >= NPTS) return;
    int b = idx[3 * p + 0];
    int x = idx[3 * p + 1];
    int y = idx[3 * p + 2];
    if ((unsigned)x >= (unsigned)Hh || (unsigned)y >= (unsigned)Ww) return;
    int cell = (b * Ww + y) * Hh + x;
    int slot = atomicAdd(&g_fill[cell], 1);
    g_pts[slot] = p;
}

// ======================= mma.sync tf32x2 GEMM, fused output scatter =======================
// smem map (bytes):
#define SM_AHI 0                     // 64x128 f32 swizzled          32768
#define SM_ALO 32768                 //                               32768
#define SM_BHI 65536                 // 256x128 f32 swizzled [n][k]  131072
#define SM_CL  196608                // 64 int
#define SM_ST  196864                // 64 int (CSR start)
#define SM_CT  197120                // 64 int (CSR count)
#define SM_RS  197376                // 64 f
#define SM_MB  197632                // 64 f  (= -rs*mu)
#define SM_GW  197888                // 256 f
#define SM_B2  198912                // 256 f
#define SMEM_TOTAL 199936

__global__ void __launch_bounds__(256, 1) k_gemm_mma(float* __restrict__ out) {
    extern __shared__ char sm[];
    float* Ah = (float*)(sm + SM_AHI);
    float* Al = (float*)(sm + SM_ALO);
    float* Bh = (float*)(sm + SM_BHI);
    int*   sCl = (int*)(sm + SM_CL);
    int*   sSt = (int*)(sm + SM_ST);
    int*   sCt = (int*)(sm + SM_CT);
    float* sRs = (float*)(sm + SM_RS);
    float* sMb = (float*)(sm + SM_MB);
    float* sGw = (float*)(sm + SM_GW);
    float* sB2 = (float*)(sm + SM_B2);

    int t = threadIdx.x;
    int lane = t & 31, wid = t >> 5;
    int grp = lane >> 2, tg = lane & 3;
    int warp_m = wid >> 2;            // 0..1
    int warp_n = wid & 3;             // 0..3
    int mbase = warp_m * 32;
    int nbase = warp_n * 64;

    // ---- load B (all 256 outputs, tf32-rounded), swizzled [n][k] ----
    for (int i = t; i < 256 * 32; i += 256) {
        int n = i >> 5, f4 = i & 31;
        float4 v = ((const float4*)g_W2)[i];
        float4 hi = make_float4(to_tf32(v.x), to_tf32(v.y), to_tf32(v.z), to_tf32(v.w));
        ((float4*)Bh)[n * 32 + (f4 ^ (n & 7))] = hi;
    }
    for (int i = t; i < COUT; i += 256) { sGw[i] = g_gw[i]; sB2[i] = g_bias2[i]; }

    int ncell  = g_ncells;
    int ntiles = (ncell + TILE_M - 1) / TILE_M;

    // A loader mapping: cell m = t>>2, quarter q = t&3
    int lm = t >> 2, lq = t & 3;
    int am0 = mbase + grp;

    for (int tile = blockIdx.x; tile < ntiles; tile += gridDim.x) {
        __syncthreads();
        if (t < TILE_M) {
            int ci = tile * TILE_M + t;
            int cid = (ci < ncell) ? g_celllist[ci] : -1;
            sCl[t] = cid;
            sSt[t] = (cid >= 0) ? g_start[cid] : 0;
            sCt[t] = (cid >= 0) ? g_cnt[cid]   : 0;
        }
        __syncthreads();

        // ---- A tile load + stats + hi/lo split + swizzled store ----
        {
            int cid = sCl[lm];
            const float4* src = (cid >= 0)
                ? (const float4*)(g_dense + (size_t)cid * CIN) : nullptr;
            float s = 0.f, ss = 0.f;
            #pragma unroll
            for (int j = 0; j < 8; j++) {
                int f4 = lq * 8 + j;
                float4 v = src ? src[f4] : make_float4(0.f, 0.f, 0.f, 0.f);
                s  += v.x + v.y + v.z + v.w;
                ss += v.x*v.x + v.y*v.y + v.z*v.z + v.w*v.w;
                float4 hi = make_float4(to_tf32(v.x), to_tf32(v.y), to_tf32(v.z), to_tf32(v.w));
                float4 lo = make_float4(to_tf32(v.x - hi.x), to_tf32(v.y - hi.y),
                                        to_tf32(v.z - hi.z), to_tf32(v.w - hi.w));
                int slot = lm * 32 + (f4 ^ (lm & 7));
                ((float4*)Ah)[slot] = hi;
                ((float4*)Al)[slot] = lo;
            }
            s  += __shfl_xor_sync(0xFFFFFFFFu, s,  1);
            ss += __shfl_xor_sync(0xFFFFFFFFu, ss, 1);
            s  += __shfl_xor_sync(0xFFFFFFFFu, s,  2);
            ss += __shfl_xor_sync(0xFFFFFFFFu, ss, 2);
            if (lq == 0) {
                float mu  = s * (1.f / CIN);
                float var = ss * (1.f / CIN) - mu * mu;
                float rs  = rsqrtf(var + EPSf);
                sRs[lm] = rs;
                sMb[lm] = -rs * mu;
            }
        }
        __syncthreads();

        // ---- mainloop: 16 k-steps, 2-term tf32 (Ah*Bh + Al*Bh) ----
        float acc[2][8][4];
        #pragma unroll
        for (int a = 0; a < 2; a++)
            #pragma unroll
            for (int b = 0; b < 8; b++)
                #pragma unroll
                for (int c = 0; c < 4; c++) acc[a][b][c] = 0.f;

        const uint32_t* Ahu = (const uint32_t*)Ah;
        const uint32_t* Alu = (const uint32_t*)Al;
        const uint32_t* Bhu = (const uint32_t*)Bh;

        #pragma unroll 4
        for (int ks = 0; ks < 16; ks++) {
            int f4a = 2 * ks, f4b = 2 * ks + 1;
            uint32_t ah[2][4], al[2][4];
            #pragma unroll
            for (int mf = 0; mf < 2; mf++) {
                int r0 = am0 + mf * 16, r1 = r0 + 8;
                ah[mf][0] = Ahu[swidx(r0, f4a, tg)];
                ah[mf][1] = Ahu[swidx(r1, f4a, tg)];
                ah[mf][2] = Ahu[swidx(r0, f4b, tg)];
                ah[mf][3] = Ahu[swidx(r1, f4b, tg)];
                al[mf][0] = Alu[swidx(r0, f4a, tg)];
                al[mf][1] = Alu[swidx(r1, f4a, tg)];
                al[mf][2] = Alu[swidx(r0, f4b, tg)];
                al[mf][3] = Alu[swidx(r1, f4b, tg)];
            }
            #pragma unroll
            for (int nf = 0; nf < 8; nf++) {
                int n0 = nbase + nf * 8 + grp;
                uint32_t bh[2];
                bh[0] = Bhu[swidx(n0, f4a, tg)];
                bh[1] = Bhu[swidx(n0, f4b, tg)];
                mma8(acc[0][nf], ah[0], bh);
                mma8(acc[1][nf], ah[1], bh);
                mma8(acc[0][nf], al[0], bh);
                mma8(acc[1][nf], al[1], bh);
            }
        }

        // ---- epilogue: affine, then write directly to every owning point ----
        #pragma unroll
        for (int mf = 0; mf < 2; mf++) {
            #pragma unroll
            for (int rr = 0; rr < 2; rr++) {
                int r = am0 + mf * 16 + rr * 8;
                int cid = sCl[r];
                if (cid < 0) continue;
                float rs = sRs[r], mb = sMb[r];
                float2 res[8];
                #pragma unroll
                for (int nf = 0; nf < 8; nf++) {
                    int n0 = nbase + nf * 8 + 2 * tg;
                    res[nf].x = rs * acc[mf][nf][rr * 2 + 0] + mb * sGw[n0]     + sB2[n0];
                    res[nf].y = rs * acc[mf][nf][rr * 2 + 1] + mb * sGw[n0 + 1] + sB2[n0 + 1];
                }
                int st = sSt[r], cn = sCt[r];
                for (int q = 0; q < cn; q++) {
                    int p = g_pts[st + q];
                    float* bp = out + (size_t)p * COUT + nbase + 2 * tg;
                    #pragma unroll
                    for (int nf = 0; nf < 8; nf++)
                        *(float2*)(bp + nf * 8) = res[nf];
                }
            }
        }
    }
}

__global__ void k_idx(const int* __restrict__ idx, float* __restrict__ out, int n) {
    int g = blockIdx.x * blockDim.x + threadIdx.x;
    if (g < n) out[g] = (float)idx[g];
}

extern "C" void kernel_launch(void* const* d_in, const int* in_sizes, int n_in,
                              void* d_out, int out_size) {
    const float* feats = (const float*)d_in[0];
    const int*   idx   = (const int*)d_in[1];
    const float* gamma = (const float*)d_in[2];
    const float* beta  = (const float*)d_in[3];
    const float* lw    = (const float*)d_in[4];
    float* out = (float*)d_out;

    cudaFuncSetAttribute(k_gemm_mma, cudaFuncAttributeMaxDynamicSharedMemorySize, SMEM_TOTAL);

    k_zero<<<17600, 256>>>();
    k_prep<<<COUT, CIN>>>(lw, gamma, beta);
    k_scatter<<<(NPTS * 32) / 256, 256>>>(feats, idx, out);
    k_compact<<<(NCELL + 255) / 256, 256>>>();
    k_fill<<<(NPTS + 255) / 256, 256>>>(idx);
    k_gemm_mma<<<148, 256, SMEM_TOTAL>>>(out);

    long long tail = (long long)out_size - (long long)NPTS * COUT;
    if (tail > 0) {
        int n = (int)((tail < (long long)NPTS * 3) ? tail : (long long)NPTS * 3);
        k_idx<<<(n + 255) / 256, 256>>>(idx, out + (size_t)NPTS * COUT, n);
    }
}

// round 9
// speedup vs baseline: 1.8514x; 1.8514x over previous
#include <cuda_runtime.h>
#include <cstdint>

#define Bb   4
#define Hh   176
#define Ww   200
#define CIN  128
#define COUT 256
#define NPTS (4096*64)
#define NCELL (Bb*Ww*Hh)
#define EPSf 1e-5f

#define TILE_M 64           // cells per GEMM tile

// -------- scratch (device globals; no allocation allowed) --------
__device__ int   g_cnt[NCELL];                      // points per cell
__device__ int   g_start[NCELL];                    // CSR segment base
__device__ int   g_fill[NCELL];                     // CSR fill cursor
__device__ int   g_pts[NPTS];                       // CSR point ids
__device__ int   g_celllist[NCELL];
__device__ int   g_ncells;
__device__ int   g_nptstotal;
__device__ float g_W2[COUT*CIN];                    // W*gamma (full fp32), [o][c]
__device__ float g_gw[COUT];                        // sum_c W2[o,c]
__device__ float g_bias2[COUT];                     // sum_c beta[c]*W[o,c]

// ======================= helpers =======================
__device__ __forceinline__ float to_tf32(float x) {
    float y; asm("cvt.rna.tf32.f32 %0, %1;" : "=f"(y) : "f"(x)); return y;
}

__device__ __forceinline__ void mma8(float* c, const uint32_t* a, const uint32_t* b) {
    asm volatile(
        "mma.sync.aligned.m16n8k8.row.col.f32.tf32.tf32.f32 "
        "{%0,%1,%2,%3}, {%4,%5,%6,%7}, {%8,%9}, {%0,%1,%2,%3};"
        : "+f"(c[0]), "+f"(c[1]), "+f"(c[2]), "+f"(c[3])
        : "r"(a[0]), "r"(a[1]), "r"(a[2]), "r"(a[3]), "r"(b[0]), "r"(b[1]));
}

// swizzled element index (floats) in a row-major [rows][128] tile
__device__ __forceinline__ int swidx(int r, int f4, int w) {
    return (r * 32 + (f4 ^ (r & 7))) * 4 + w;
}

// ======================= small kernels =======================
__global__ void k_init() {
    int i = blockIdx.x * blockDim.x + threadIdx.x;
    int stride = gridDim.x * blockDim.x;
    for (int j = i; j < NCELL; j += stride) {
        g_cnt[j] = 0;
        g_start[j] = 0;
        g_fill[j] = 0;
    }
    if (i == 0) { g_ncells = 0; g_nptstotal = 0; }
}

__global__ void k_prep(const float* __restrict__ lw,
                       const float* __restrict__ gamma,
                       const float* __restrict__ beta) {
    int o = blockIdx.x;
    int c = threadIdx.x;
    float w  = lw[o * CIN + c];
    float w2 = w * gamma[c];
    g_W2[o * CIN + c] = w2;
    float gwv = w2;
    float b2  = w * beta[c];
    for (int s = 16; s > 0; s >>= 1) {
        gwv += __shfl_xor_sync(0xFFFFFFFFu, gwv, s);
        b2  += __shfl_xor_sync(0xFFFFFFFFu, b2,  s);
    }
    __shared__ float sg[4], sb[4];
    if ((c & 31) == 0) { sg[c >> 5] = gwv; sb[c >> 5] = b2; }
    __syncthreads();
    if (c == 0) {
        g_gw[o]    = sg[0] + sg[1] + sg[2] + sg[3];
        g_bias2[o] = sb[0] + sb[1] + sb[2] + sb[3];
    }
}

// count points per cell (1 warp/point); invalid points zero their output row
__global__ void k_count(const int* __restrict__ idx, float* __restrict__ out) {
    int g = blockIdx.x * blockDim.x + threadIdx.x;
    int p = g >> 5;
    int l = g & 31;
    if (p >= NPTS) return;
    int b = idx[3 * p + 0];
    int x = idx[3 * p + 1];
    int y = idx[3 * p + 2];
    if ((unsigned)x >= (unsigned)Hh || (unsigned)y >= (unsigned)Ww) {
        float4 z = make_float4(0.f, 0.f, 0.f, 0.f);
        float4* o4 = (float4*)(out + (size_t)p * COUT);
        o4[2 * l]     = z;
        o4[2 * l + 1] = z;
        return;
    }
    if (l == 0) {
        int cell = (b * Ww + y) * Hh + x;
        atomicAdd(&g_cnt[cell], 1);
    }
}

// compact occupied cells + CSR segments; warp-aggregated atomics
__global__ void k_compact() {
    int c = blockIdx.x * blockDim.x + threadIdx.x;
    int lane = threadIdx.x & 31;
    bool occ = (c < NCELL) && (g_cnt[c] > 0);
    int cnt = occ ? g_cnt[c] : 0;
    unsigned m = __ballot_sync(0xFFFFFFFFu, occ);
    // inclusive warp scan of cnt
    int scan = cnt;
    #pragma unroll
    for (int d = 1; d < 32; d <<= 1) {
        int v = __shfl_up_sync(0xFFFFFFFFu, scan, d);
        if (lane >= d) scan += v;
    }
    int total = __shfl_sync(0xFFFFFFFFu, scan, 31);
    int excl  = scan - cnt;
    int nOcc  = __popc(m);
    int rank  = __popc(m & ((1u << lane) - 1));
    int b1 = 0, b2 = 0;
    if (lane == 0 && nOcc > 0) {
        b1 = atomicAdd(&g_ncells, nOcc);
        b2 = atomicAdd(&g_nptstotal, total);
    }
    b1 = __shfl_sync(0xFFFFFFFFu, b1, 0);
    b2 = __shfl_sync(0xFFFFFFFFu, b2, 0);
    if (occ) {
        g_celllist[b1 + rank] = c;
        g_start[c] = b2 + excl;
        g_fill[c]  = b2 + excl;
    }
}

// CSR fill: record which points own each cell
__global__ void k_fill(const int* __restrict__ idx) {
    int p = blockIdx.x * blockDim.x + threadIdx.x;
    if (p >= NPTS) return;
    int b = idx[3 * p + 0];
    int x = idx[3 * p + 1];
    int y = idx[3 * p + 2];
    if ((unsigned)x >= (unsigned)Hh || (unsigned)y >= (unsigned)Ww) return;
    int cell = (b * Ww + y) * Hh + x;
    int slot = atomicAdd(&g_fill[cell], 1);
    g_pts[slot] = p;
}

// ======================= mma.sync tf32x2 GEMM: CSR gather-sum -> MMA -> fused scatter =======================
// smem map (bytes):
#define SM_AHI 0                     // 64x128 f32 swizzled          32768
#define SM_ALO 32768                 //                               32768
#define SM_BHI 65536                 // 256x128 f32 swizzled [n][k]  131072
#define SM_CL  196608                // 64 int
#define SM_ST  196864                // 64 int (CSR start)
#define SM_CT  197120                // 64 int (CSR count)
#define SM_RS  197376                // 64 f
#define SM_MB  197632                // 64 f  (= -rs*mu)
#define SM_GW  197888                // 256 f
#define SM_B2  198912                // 256 f
#define SMEM_TOTAL 199936

__global__ void __launch_bounds__(256, 1) k_gemm_mma(const float* __restrict__ feats,
                                                     float* __restrict__ out) {
    extern __shared__ char sm[];
    float* Ah = (float*)(sm + SM_AHI);
    float* Al = (float*)(sm + SM_ALO);
    float* Bh = (float*)(sm + SM_BHI);
    int*   sCl = (int*)(sm + SM_CL);
    int*   sSt = (int*)(sm + SM_ST);
    int*   sCt = (int*)(sm + SM_CT);
    float* sRs = (float*)(sm + SM_RS);
    float* sMb = (float*)(sm + SM_MB);
    float* sGw = (float*)(sm + SM_GW);
    float* sB2 = (float*)(sm + SM_B2);

    int t = threadIdx.x;
    int lane = t & 31, wid = t >> 5;
    int grp = lane >> 2, tg = lane & 3;
    int warp_m = wid >> 2;            // 0..1
    int warp_n = wid & 3;             // 0..3
    int mbase = warp_m * 32;
    int nbase = warp_n * 64;

    // ---- load B (all 256 outputs, tf32-rounded), swizzled [n][k] ----
    for (int i = t; i < 256 * 32; i += 256) {
        int n = i >> 5, f4 = i & 31;
        float4 v = ((const float4*)g_W2)[i];
        float4 hi = make_float4(to_tf32(v.x), to_tf32(v.y), to_tf32(v.z), to_tf32(v.w));
        ((float4*)Bh)[n * 32 + (f4 ^ (n & 7))] = hi;
    }
    for (int i = t; i < COUT; i += 256) { sGw[i] = g_gw[i]; sB2[i] = g_bias2[i]; }

    int ncell  = g_ncells;
    int ntiles = (ncell + TILE_M - 1) / TILE_M;

    // A builder mapping: cell m = t>>2, quarter q = t&3 (floats lq*32..lq*32+31)
    int lm = t >> 2, lq = t & 3;
    int am0 = mbase + grp;

    for (int tile = blockIdx.x; tile < ntiles; tile += gridDim.x) {
        __syncthreads();
        if (t < TILE_M) {
            int ci = tile * TILE_M + t;
            int cid = (ci < ncell) ? g_celllist[ci] : -1;
            sCl[t] = cid;
            sSt[t] = (cid >= 0) ? g_start[cid] : 0;
            sCt[t] = (cid >= 0) ? g_cnt[cid]   : 0;
        }
        __syncthreads();

        // ---- A tile: CSR gather-sum in registers + stats + hi/lo split + swizzled store ----
        {
            int st = sSt[lm], cn = sCt[lm];
            float4 a[8];
            #pragma unroll
            for (int j = 0; j < 8; j++) a[j] = make_float4(0.f, 0.f, 0.f, 0.f);
            for (int q = 0; q < cn; q++) {
                int p = g_pts[st + q];
                const float4* src = (const float4*)(feats + (size_t)p * CIN) + lq * 8;
                #pragma unroll
                for (int j = 0; j < 8; j++) {
                    float4 v = src[j];
                    a[j].x += v.x; a[j].y += v.y; a[j].z += v.z; a[j].w += v.w;
                }
            }
            float s = 0.f, ss = 0.f;
            #pragma unroll
            for (int j = 0; j < 8; j++) {
                float4 v = a[j];
                s  += v.x + v.y + v.z + v.w;
                ss += v.x*v.x + v.y*v.y + v.z*v.z + v.w*v.w;
                float4 hi = make_float4(to_tf32(v.x), to_tf32(v.y), to_tf32(v.z), to_tf32(v.w));
                float4 lo = make_float4(to_tf32(v.x - hi.x), to_tf32(v.y - hi.y),
                                        to_tf32(v.z - hi.z), to_tf32(v.w - hi.w));
                int f4 = lq * 8 + j;
                int slot = lm * 32 + (f4 ^ (lm & 7));
                ((float4*)Ah)[slot] = hi;
                ((float4*)Al)[slot] = lo;
            }
            s  += __shfl_xor_sync(0xFFFFFFFFu, s,  1);
            ss += __shfl_xor_sync(0xFFFFFFFFu, ss, 1);
            s  += __shfl_xor_sync(0xFFFFFFFFu, s,  2);
            ss += __shfl_xor_sync(0xFFFFFFFFu, ss, 2);
            if (lq == 0) {
                float mu  = s * (1.f / CIN);
                float var = ss * (1.f / CIN) - mu * mu;
                float rs  = rsqrtf(var + EPSf);
                sRs[lm] = rs;
                sMb[lm] = -rs * mu;
            }
        }
        __syncthreads();

        // ---- mainloop: 16 k-steps, 2-term tf32 (Ah*Bh + Al*Bh) ----
        float acc[2][8][4];
        #pragma unroll
        for (int a = 0; a < 2; a++)
            #pragma unroll
            for (int b = 0; b < 8; b++)
                #pragma unroll
                for (int c = 0; c < 4; c++) acc[a][b][c] = 0.f;

        const uint32_t* Ahu = (const uint32_t*)Ah;
        const uint32_t* Alu = (const uint32_t*)Al;
        const uint32_t* Bhu = (const uint32_t*)Bh;

        #pragma unroll 4
        for (int ks = 0; ks < 16; ks++) {
            int f4a = 2 * ks, f4b = 2 * ks + 1;
            uint32_t ah[2][4], al[2][4];
            #pragma unroll
            for (int mf = 0; mf < 2; mf++) {
                int r0 = am0 + mf * 16, r1 = r0 + 8;
                ah[mf][0] = Ahu[swidx(r0, f4a, tg)];
                ah[mf][1] = Ahu[swidx(r1, f4a, tg)];
                ah[mf][2] = Ahu[swidx(r0, f4b, tg)];
                ah[mf][3] = Ahu[swidx(r1, f4b, tg)];
                al[mf][0] = Alu[swidx(r0, f4a, tg)];
                al[mf][1] = Alu[swidx(r1, f4a, tg)];
                al[mf][2] = Alu[swidx(r0, f4b, tg)];
                al[mf][3] = Alu[swidx(r1, f4b, tg)];
            }
            #pragma unroll
            for (int nf = 0; nf < 8; nf++) {
                int n0 = nbase + nf * 8 + grp;
                uint32_t bh[2];
                bh[0] = Bhu[swidx(n0, f4a, tg)];
                bh[1] = Bhu[swidx(n0, f4b, tg)];
                mma8(acc[0][nf], ah[0], bh);
                mma8(acc[1][nf], ah[1], bh);
                mma8(acc[0][nf], al[0], bh);
                mma8(acc[1][nf], al[1], bh);
            }
        }

        // ---- epilogue: affine, then write directly to every owning point ----
        #pragma unroll
        for (int mf = 0; mf < 2; mf++) {
            #pragma unroll
            for (int rr = 0; rr < 2; rr++) {
                int r = am0 + mf * 16 + rr * 8;
                int cid = sCl[r];
                if (cid < 0) continue;
                float rs = sRs[r], mb = sMb[r];
                float2 res[8];
                #pragma unroll
                for (int nf = 0; nf < 8; nf++) {
                    int n0 = nbase + nf * 8 + 2 * tg;
                    res[nf].x = rs * acc[mf][nf][rr * 2 + 0] + mb * sGw[n0]     + sB2[n0];
                    res[nf].y = rs * acc[mf][nf][rr * 2 + 1] + mb * sGw[n0 + 1] + sB2[n0 + 1];
                }
                int st = sSt[r], cn = sCt[r];
                for (int q = 0; q < cn; q++) {
                    int p = g_pts[st + q];
                    float* bp = out + (size_t)p * COUT + nbase + 2 * tg;
                    #pragma unroll
                    for (int nf = 0; nf < 8; nf++)
                        *(float2*)(bp + nf * 8) = res[nf];
                }
            }
        }
    }
}

__global__ void k_idx(const int* __restrict__ idx, float* __restrict__ out, int n) {
    int g = blockIdx.x * blockDim.x + threadIdx.x;
    if (g < n) out[g] = (float)idx[g];
}

extern "C" void kernel_launch(void* const* d_in, const int* in_sizes, int n_in,
                              void* d_out, int out_size) {
    const float* feats = (const float*)d_in[0];
    const int*   idx   = (const int*)d_in[1];
    const float* gamma = (const float*)d_in[2];
    const float* beta  = (const float*)d_in[3];
    const float* lw    = (const float*)d_in[4];
    float* out = (float*)d_out;

    cudaFuncSetAttribute(k_gemm_mma, cudaFuncAttributeMaxDynamicSharedMemorySize, SMEM_TOTAL);

    k_init<<<550, 256>>>();
    k_prep<<<COUT, CIN>>>(lw, gamma, beta);
    k_count<<<(NPTS * 32) / 256, 256>>>(idx, out);
    k_compact<<<(NCELL + 255) / 256, 256>>>();
    k_fill<<<(NPTS + 255) / 256, 256>>>(idx);
    k_gemm_mma<<<148, 256, SMEM_TOTAL>>>(feats, out);

    long long tail = (long long)out_size - (long long)NPTS * COUT;
    if (tail > 0) {
        int n = (int)((tail < (long long)NPTS * 3) ? tail : (long long)NPTS * 3);
        k_idx<<<(n + 255) / 256, 256>>>(idx, out + (size_t)NPTS * COUT, n);
    }
}

// round 10
// speedup vs baseline: 2.0723x; 1.1193x over previous
#include <cuda_runtime.h>
#include <cstdint>

#define Bb   4
#define Hh   176
#define Ww   200
#define CIN  128
#define COUT 256
#define NPTS (4096*64)
#define NCELL (Bb*Ww*Hh)
#define EPSf 1e-5f

#define TILE_M 64           // cells per GEMM tile

// -------- scratch (device globals; no allocation allowed) --------
__device__ int   g_cnt[NCELL];                      // points per cell
__device__ int   g_start[NCELL];                    // CSR segment base
__device__ int   g_fill[NCELL];                     // CSR fill cursor
__device__ int   g_pts[NPTS];                       // CSR point ids
__device__ int   g_celllist[NCELL];
__device__ int   g_ncells;
__device__ int   g_nptstotal;
__device__ float g_W2[COUT*CIN];                    // W*gamma (full fp32), [o][c]
__device__ float g_gw[COUT];                        // sum_c W2[o,c]
__device__ float g_bias2[COUT];                     // sum_c beta[c]*W[o,c]

// ======================= helpers =======================
// pack two f32 into bf16x2: low half = a0 (even k), high half = a1 (odd k)
__device__ __forceinline__ uint32_t pack_bf2(float a0, float a1) {
    uint32_t r;
    asm("cvt.rn.bf16x2.f32 %0, %1, %2;" : "=r"(r) : "f"(a1), "f"(a0));
    return r;
}
__device__ __forceinline__ float bf_lo(uint32_t v) { return __uint_as_float(v << 16); }
__device__ __forceinline__ float bf_hi(uint32_t v) { return __uint_as_float(v & 0xFFFF0000u); }

// m16n8k16 bf16 MMA, f32 accum
__device__ __forceinline__ void mma16(float* c, const uint32_t* a, const uint32_t* b) {
    asm volatile(
        "mma.sync.aligned.m16n8k16.row.col.f32.bf16.bf16.f32 "
        "{%0,%1,%2,%3}, {%4,%5,%6,%7}, {%8,%9}, {%0,%1,%2,%3};"
        : "+f"(c[0]), "+f"(c[1]), "+f"(c[2]), "+f"(c[3])
        : "r"(a[0]), "r"(a[1]), "r"(a[2]), "r"(a[3]), "r"(b[0]), "r"(b[1]));
}

// swizzled WORD index in a row-major [rows][64-word] bf16x2 tile (row = 128 bf16)
// w = word 0..63; f4 = w>>2 XOR'd with (r&7)
__device__ __forceinline__ int swb(int r, int w) {
    return (r * 16 + ((w >> 2) ^ (r & 7))) * 4 + (w & 3);
}

// ======================= small kernels =======================
__global__ void k_init() {
    int i = blockIdx.x * blockDim.x + threadIdx.x;
    int stride = gridDim.x * blockDim.x;
    for (int j = i; j < NCELL; j += stride) {
        g_cnt[j] = 0;
        g_start[j] = 0;
        g_fill[j] = 0;
    }
    if (i == 0) { g_ncells = 0; g_nptstotal = 0; }
}

__global__ void k_prep(const float* __restrict__ lw,
                       const float* __restrict__ gamma,
                       const float* __restrict__ beta) {
    int o = blockIdx.x;
    int c = threadIdx.x;
    float w  = lw[o * CIN + c];
    float w2 = w * gamma[c];
    g_W2[o * CIN + c] = w2;
    float gwv = w2;
    float b2  = w * beta[c];
    for (int s = 16; s > 0; s >>= 1) {
        gwv += __shfl_xor_sync(0xFFFFFFFFu, gwv, s);
        b2  += __shfl_xor_sync(0xFFFFFFFFu, b2,  s);
    }
    __shared__ float sg[4], sb[4];
    if ((c & 31) == 0) { sg[c >> 5] = gwv; sb[c >> 5] = b2; }
    __syncthreads();
    if (c == 0) {
        g_gw[o]    = sg[0] + sg[1] + sg[2] + sg[3];
        g_bias2[o] = sb[0] + sb[1] + sb[2] + sb[3];
    }
}

// count points per cell (1 warp/point); invalid points zero their output row
__global__ void k_count(const int* __restrict__ idx, float* __restrict__ out) {
    int g = blockIdx.x * blockDim.x + threadIdx.x;
    int p = g >> 5;
    int l = g & 31;
    if (p >= NPTS) return;
    int cell = -1;
    if (l == 0) {
        int b = idx[3 * p + 0];
        int x = idx[3 * p + 1];
        int y = idx[3 * p + 2];
        if ((unsigned)x < (unsigned)Hh && (unsigned)y < (unsigned)Ww)
            cell = (b * Ww + y) * Hh + x;
    }
    cell = __shfl_sync(0xFFFFFFFFu, cell, 0);
    if (cell < 0) {
        float4 z = make_float4(0.f, 0.f, 0.f, 0.f);
        float4* o4 = (float4*)(out + (size_t)p * COUT);
        o4[2 * l]     = z;
        o4[2 * l + 1] = z;
        return;
    }
    if (l == 0) atomicAdd(&g_cnt[cell], 1);
}

// compact occupied cells + CSR segments; warp-aggregated atomics
__global__ void k_compact() {
    int c = blockIdx.x * blockDim.x + threadIdx.x;
    int lane = threadIdx.x & 31;
    bool occ = (c < NCELL) && (g_cnt[c] > 0);
    int cnt = occ ? g_cnt[c] : 0;
    unsigned m = __ballot_sync(0xFFFFFFFFu, occ);
    int scan = cnt;
    #pragma unroll
    for (int d = 1; d < 32; d <<= 1) {
        int v = __shfl_up_sync(0xFFFFFFFFu, scan, d);
        if (lane >= d) scan += v;
    }
    int total = __shfl_sync(0xFFFFFFFFu, scan, 31);
    int excl  = scan - cnt;
    int nOcc  = __popc(m);
    int rank  = __popc(m & ((1u << lane) - 1));
    int b1 = 0, b2 = 0;
    if (lane == 0 && nOcc > 0) {
        b1 = atomicAdd(&g_ncells, nOcc);
        b2 = atomicAdd(&g_nptstotal, total);
    }
    b1 = __shfl_sync(0xFFFFFFFFu, b1, 0);
    b2 = __shfl_sync(0xFFFFFFFFu, b2, 0);
    if (occ) {
        g_celllist[b1 + rank] = c;
        g_start[c] = b2 + excl;
        g_fill[c]  = b2 + excl;
    }
}

// CSR fill: record which points own each cell
__global__ void k_fill(const int* __restrict__ idx) {
    int p = blockIdx.x * blockDim.x + threadIdx.x;
    if (p >= NPTS) return;
    int b = idx[3 * p + 0];
    int x = idx[3 * p + 1];
    int y = idx[3 * p + 2];
    if ((unsigned)x >= (unsigned)Hh || (unsigned)y >= (unsigned)Ww) return;
    int cell = (b * Ww + y) * Hh + x;
    int slot = atomicAdd(&g_fill[cell], 1);
    g_pts[slot] = p;
}

// ======== bf16 3-term m16n8k16 GEMM: CSR gather-sum -> MMA -> fused scatter ========
// smem map (bytes): bf16x2 tiles, 64 words (=128 bf16) per row
#define SM_AHI 0                     // 64x64w   16384
#define SM_ALO 16384                 //          16384
#define SM_BHI 32768                 // 256x64w  65536
#define SM_BLO 98304                 //          65536
#define SM_CL  163840                // 64 int
#define SM_ST  164096
#define SM_CT  164352
#define SM_RS  164608
#define SM_MB  164864
#define SM_GW  165120                // 256 f
#define SM_B2  166144                // 256 f
#define SMEM_TOTAL 167168

__global__ void __launch_bounds__(256, 1) k_gemm_mma(const float* __restrict__ feats,
                                                     float* __restrict__ out) {
    extern __shared__ char sm[];
    uint32_t* AhW = (uint32_t*)(sm + SM_AHI);
    uint32_t* AlW = (uint32_t*)(sm + SM_ALO);
    uint32_t* BhW = (uint32_t*)(sm + SM_BHI);
    uint32_t* BlW = (uint32_t*)(sm + SM_BLO);
    int*   sCl = (int*)(sm + SM_CL);
    int*   sSt = (int*)(sm + SM_ST);
    int*   sCt = (int*)(sm + SM_CT);
    float* sRs = (float*)(sm + SM_RS);
    float* sMb = (float*)(sm + SM_MB);
    float* sGw = (float*)(sm + SM_GW);
    float* sB2 = (float*)(sm + SM_B2);

    int t = threadIdx.x;
    int lane = t & 31, wid = t >> 5;
    int grp = lane >> 2, tg = lane & 3;
    int warp_m = wid >> 2;            // 0..1
    int warp_n = wid & 3;             // 0..3
    int mbase = warp_m * 32;
    int nbase = warp_n * 64;

    // ---- load B: hi/lo bf16 split, swizzled [n][k] ----
    for (int i = t; i < 256 * 32; i += 256) {
        int n = i >> 5, f4 = i & 31;               // f4 = float4 index (4 fp32 = 2 words)
        float4 v = ((const float4*)g_W2)[i];
        uint32_t h0 = pack_bf2(v.x, v.y);
        uint32_t h1 = pack_bf2(v.z, v.w);
        uint32_t l0 = pack_bf2(v.x - bf_lo(h0), v.y - bf_hi(h0));
        uint32_t l1 = pack_bf2(v.z - bf_lo(h1), v.w - bf_hi(h1));
        int w = 2 * f4;                            // even word; both words share f4 slot
        int s0 = swb(n, w);
        BhW[s0] = h0; BhW[s0 + 1] = h1;
        BlW[s0] = l0; BlW[s0 + 1] = l1;
    }
    for (int i = t; i < COUT; i += 256) { sGw[i] = g_gw[i]; sB2[i] = g_bias2[i]; }

    int ncell  = g_ncells;
    int ntiles = (ncell + TILE_M - 1) / TILE_M;

    // A builder mapping: cell m = t>>2, quarter q = t&3 (floats lq*32..lq*32+31)
    int lm = t >> 2, lq = t & 3;
    int am0 = mbase + grp;

    for (int tile = blockIdx.x; tile < ntiles; tile += gridDim.x) {
        __syncthreads();
        if (t < TILE_M) {
            int ci = tile * TILE_M + t;
            int cid = (ci < ncell) ? g_celllist[ci] : -1;
            sCl[t] = cid;
            sSt[t] = (cid >= 0) ? g_start[cid] : 0;
            sCt[t] = (cid >= 0) ? g_cnt[cid]   : 0;
        }
        __syncthreads();

        // ---- A tile: CSR gather-sum in registers + stats + bf16 hi/lo + swizzled store ----
        {
            int st = sSt[lm], cn = sCt[lm];
            float4 a[8];
            #pragma unroll
            for (int j = 0; j < 8; j++) a[j] = make_float4(0.f, 0.f, 0.f, 0.f);
            for (int q = 0; q < cn; q++) {
                int p = g_pts[st + q];
                const float4* src = (const float4*)(feats + (size_t)p * CIN) + lq * 8;
                #pragma unroll
                for (int j = 0; j < 8; j++) {
                    float4 v = src[j];
                    a[j].x += v.x; a[j].y += v.y; a[j].z += v.z; a[j].w += v.w;
                }
            }
            float s = 0.f, ss = 0.f;
            #pragma unroll
            for (int j = 0; j < 8; j++) {
                float4 v = a[j];
                s  += v.x + v.y + v.z + v.w;
                ss += v.x*v.x + v.y*v.y + v.z*v.z + v.w*v.w;
                uint32_t h0 = pack_bf2(v.x, v.y);
                uint32_t h1 = pack_bf2(v.z, v.w);
                uint32_t l0 = pack_bf2(v.x - bf_lo(h0), v.y - bf_hi(h0));
                uint32_t l1 = pack_bf2(v.z - bf_lo(h1), v.w - bf_hi(h1));
                int w = 2 * (lq * 8 + j);
                int s0 = swb(lm, w);
                AhW[s0] = h0; AhW[s0 + 1] = h1;
                AlW[s0] = l0; AlW[s0 + 1] = l1;
            }
            s  += __shfl_xor_sync(0xFFFFFFFFu, s,  1);
            ss += __shfl_xor_sync(0xFFFFFFFFu, ss, 1);
            s  += __shfl_xor_sync(0xFFFFFFFFu, s,  2);
            ss += __shfl_xor_sync(0xFFFFFFFFu, ss, 2);
            if (lq == 0) {
                float mu  = s * (1.f / CIN);
                float var = ss * (1.f / CIN) - mu * mu;
                float rs  = rsqrtf(var + EPSf);
                sRs[lm] = rs;
                sMb[lm] = -rs * mu;
            }
        }
        __syncthreads();

        // ---- mainloop: 8 k16-steps, 3-term bf16 (AhBh + AlBh + AhBl) ----
        float acc[2][8][4];
        #pragma unroll
        for (int a = 0; a < 2; a++)
            #pragma unroll
            for (int b = 0; b < 8; b++)
                #pragma unroll
                for (int c = 0; c < 4; c++) acc[a][b][c] = 0.f;

        #pragma unroll
        for (int ks = 0; ks < 8; ks++) {
            int w0 = 8 * ks + tg;      // frag word (k pair) low
            int w1 = w0 + 4;           // frag word high
            uint32_t ah[2][4], al[2][4];
            #pragma unroll
            for (int mf = 0; mf < 2; mf++) {
                int r0 = am0 + mf * 16, r1 = r0 + 8;
                ah[mf][0] = AhW[swb(r0, w0)];
                ah[mf][1] = AhW[swb(r1, w0)];
                ah[mf][2] = AhW[swb(r0, w1)];
                ah[mf][3] = AhW[swb(r1, w1)];
                al[mf][0] = AlW[swb(r0, w0)];
                al[mf][1] = AlW[swb(r1, w0)];
                al[mf][2] = AlW[swb(r0, w1)];
                al[mf][3] = AlW[swb(r1, w1)];
            }
            #pragma unroll
            for (int nf = 0; nf < 8; nf++) {
                int n0 = nbase + nf * 8 + grp;
                uint32_t bh[2], bl[2];
                bh[0] = BhW[swb(n0, w0)];
                bh[1] = BhW[swb(n0, w1)];
                bl[0] = BlW[swb(n0, w0)];
                bl[1] = BlW[swb(n0, w1)];
                mma16(acc[0][nf], ah[0], bh);
                mma16(acc[1][nf], ah[1], bh);
                mma16(acc[0][nf], al[0], bh);
                mma16(acc[1][nf], al[1], bh);
                mma16(acc[0][nf], ah[0], bl);
                mma16(acc[1][nf], ah[1], bl);
            }
        }

        // ---- epilogue: affine, then write directly to every owning point ----
        #pragma unroll
        for (int mf = 0; mf < 2; mf++) {
            #pragma unroll
            for (int rr = 0; rr < 2; rr++) {
                int r = am0 + mf * 16 + rr * 8;
                int cid = sCl[r];
                if (cid < 0) continue;
                float rs = sRs[r], mb = sMb[r];
                float2 res[8];
                #pragma unroll
                for (int nf = 0; nf < 8; nf++) {
                    int n0 = nbase + nf * 8 + 2 * tg;
                    res[nf].x = rs * acc[mf][nf][rr * 2 + 0] + mb * sGw[n0]     + sB2[n0];
                    res[nf].y = rs * acc[mf][nf][rr * 2 + 1] + mb * sGw[n0 + 1] + sB2[n0 + 1];
                }
                int st = sSt[r], cn = sCt[r];
                for (int q = 0; q < cn; q++) {
                    int p = g_pts[st + q];
                    float* bp = out + (size_t)p * COUT + nbase + 2 * tg;
                    #pragma unroll
                    for (int nf = 0; nf < 8; nf++)
                        *(float2*)(bp + nf * 8) = res[nf];
                }
            }
        }
    }
}

__global__ void k_idx(const int* __restrict__ idx, float* __restrict__ out, int n) {
    int g = blockIdx.x * blockDim.x + threadIdx.x;
    if (g < n) out[g] = (float)idx[g];
}

extern "C" void kernel_launch(void* const* d_in, const int* in_sizes, int n_in,
                              void* d_out, int out_size) {
    const float* feats = (const float*)d_in[0];
    const int*   idx   = (const int*)d_in[1];
    const float* gamma = (const float*)d_in[2];
    const float* beta  = (const float*)d_in[3];
    const float* lw    = (const float*)d_in[4];
    float* out = (float*)d_out;

    cudaFuncSetAttribute(k_gemm_mma, cudaFuncAttributeMaxDynamicSharedMemorySize, SMEM_TOTAL);

    k_init<<<550, 256>>>();
    k_prep<<<COUT, CIN>>>(lw, gamma, beta);
    k_count<<<(NPTS * 32) / 256, 256>>>(idx, out);
    k_compact<<<(NCELL + 255) / 256, 256>>>();
    k_fill<<<(NPTS + 255) / 256, 256>>>(idx);
    k_gemm_mma<<<148, 256, SMEM_TOTAL>>>(feats, out);

    long long tail = (long long)out_size - (long long)NPTS * COUT;
    if (tail > 0) {
        int n = (int)((tail < (long long)NPTS * 3) ? tail : (long long)NPTS * 3);
        k_idx<<<(n + 255) / 256, 256>>>(idx, out + (size_t)NPTS * COUT, n);
    }
}

// round 12
// speedup vs baseline: 2.6537x; 1.2806x over previous
#include <cuda_runtime.h>
#include <cuda_fp16.h>
#include <cstdint>

#define Bb   4
#define Hh   176
#define Ww   200
#define CIN  128
#define COUT 256
#define NPTS (4096*64)
#define NCELL (Bb*Ww*Hh)
#define EPSf 1e-5f

#define TILE_M 64           // cells per GEMM tile

// -------- scratch (device globals; no allocation allowed) --------
__device__ int   g_cnt[NCELL];                      // points per cell
__device__ int   g_start[NCELL];                    // CSR segment base
__device__ int   g_fill[NCELL];                     // CSR fill cursor
__device__ int   g_pts[NPTS];                       // CSR point ids
__device__ int   g_celllist[NCELL];
__device__ int   g_ncells;
__device__ int   g_nptstotal;
__device__ float g_W2[COUT*CIN];                    // W*gamma (full fp32), [o][c]
__device__ float g_gw[COUT];                        // sum_c W2[o,c]
__device__ float g_bias2[COUT];                     // sum_c beta[c]*W[o,c]

// ======================= helpers =======================
// pack two f32 -> f16x2 (lo = a0, hi = a1) and residuals
__device__ __forceinline__ uint32_t pack_h2(float a0, float a1) {
    __half2 h = __halves2half2(__float2half_rn(a0), __float2half_rn(a1));
    return *(uint32_t*)&h;
}
__device__ __forceinline__ float h2_lo_f(uint32_t v) {
    __half2 h = *(__half2*)&v; return __half2float(__low2half(h));
}
__device__ __forceinline__ float h2_hi_f(uint32_t v) {
    __half2 h = *(__half2*)&v; return __half2float(__high2half(h));
}

// m16n8k16 fp16 MMA, f32 accum
__device__ __forceinline__ void mma16(float* c, const uint32_t* a, const uint32_t* b) {
    asm volatile(
        "mma.sync.aligned.m16n8k16.row.col.f32.f16.f16.f32 "
        "{%0,%1,%2,%3}, {%4,%5,%6,%7}, {%8,%9}, {%0,%1,%2,%3};"
        : "+f"(c[0]), "+f"(c[1]), "+f"(c[2]), "+f"(c[3])
        : "r"(a[0]), "r"(a[1]), "r"(a[2]), "r"(a[3]), "r"(b[0]), "r"(b[1]));
}

// swizzled WORD index in a row-major [rows][64-word] f16x2 tile (row = 128 halves)
__device__ __forceinline__ int swb(int r, int w) {
    return (r * 16 + ((w >> 2) ^ (r & 7))) * 4 + (w & 3);
}

// ======================= small kernels =======================
__global__ void k_init() {
    int i = blockIdx.x * blockDim.x + threadIdx.x;
    int stride = gridDim.x * blockDim.x;
    for (int j = i; j < NCELL; j += stride) {
        g_cnt[j] = 0;
        g_start[j] = 0;
        g_fill[j] = 0;
    }
    if (i == 0) { g_ncells = 0; g_nptstotal = 0; }
}

__global__ void k_prep(const float* __restrict__ lw,
                       const float* __restrict__ gamma,
                       const float* __restrict__ beta) {
    int o = blockIdx.x;
    int c = threadIdx.x;
    float w  = lw[o * CIN + c];
    float w2 = w * gamma[c];
    g_W2[o * CIN + c] = w2;
    float gwv = w2;
    float b2  = w * beta[c];
    for (int s = 16; s > 0; s >>= 1) {
        gwv += __shfl_xor_sync(0xFFFFFFFFu, gwv, s);
        b2  += __shfl_xor_sync(0xFFFFFFFFu, b2,  s);
    }
    __shared__ float sg[4], sb[4];
    if ((c & 31) == 0) { sg[c >> 5] = gwv; sb[c >> 5] = b2; }
    __syncthreads();
    if (c == 0) {
        g_gw[o]    = sg[0] + sg[1] + sg[2] + sg[3];
        g_bias2[o] = sb[0] + sb[1] + sb[2] + sb[3];
    }
}

// count points per cell (1 warp/point); invalid points zero their output row
__global__ void k_count(const int* __restrict__ idx, float* __restrict__ out) {
    int g = blockIdx.x * blockDim.x + threadIdx.x;
    int p = g >> 5;
    int l = g & 31;
    if (p >= NPTS) return;
    int cell = -1;
    if (l == 0) {
        int b = idx[3 * p + 0];
        int x = idx[3 * p + 1];
        int y = idx[3 * p + 2];
        if ((unsigned)x < (unsigned)Hh && (unsigned)y < (unsigned)Ww)
            cell = (b * Ww + y) * Hh + x;
    }
    cell = __shfl_sync(0xFFFFFFFFu, cell, 0);
    if (cell < 0) {
        float4 z = make_float4(0.f, 0.f, 0.f, 0.f);
        float4* o4 = (float4*)(out + (size_t)p * COUT);
        o4[2 * l]     = z;
        o4[2 * l + 1] = z;
        return;
    }
    if (l == 0) atomicAdd(&g_cnt[cell], 1);
}

// compact occupied cells + CSR segments; warp-aggregated atomics
__global__ void k_compact() {
    int c = blockIdx.x * blockDim.x + threadIdx.x;
    int lane = threadIdx.x & 31;
    bool occ = (c < NCELL) && (g_cnt[c] > 0);
    int cnt = occ ? g_cnt[c] : 0;
    unsigned m = __ballot_sync(0xFFFFFFFFu, occ);
    int scan = cnt;
    #pragma unroll
    for (int d = 1; d < 32; d <<= 1) {
        int v = __shfl_up_sync(0xFFFFFFFFu, scan, d);
        if (lane >= d) scan += v;
    }
    int total = __shfl_sync(0xFFFFFFFFu, scan, 31);
    int excl  = scan - cnt;
    int nOcc  = __popc(m);
    int rank  = __popc(m & ((1u << lane) - 1));
    int b1 = 0, b2 = 0;
    if (lane == 0 && nOcc > 0) {
        b1 = atomicAdd(&g_ncells, nOcc);
        b2 = atomicAdd(&g_nptstotal, total);
    }
    b1 = __shfl_sync(0xFFFFFFFFu, b1, 0);
    b2 = __shfl_sync(0xFFFFFFFFu, b2, 0);
    if (occ) {
        g_celllist[b1 + rank] = c;
        g_start[c] = b2 + excl;
        g_fill[c]  = b2 + excl;
    }
}

// CSR fill: record which points own each cell
__global__ void k_fill(const int* __restrict__ idx) {
    int p = blockIdx.x * blockDim.x + threadIdx.x;
    if (p >= NPTS) return;
    int b = idx[3 * p + 0];
    int x = idx[3 * p + 1];
    int y = idx[3 * p + 2];
    if ((unsigned)x >= (unsigned)Hh || (unsigned)y >= (unsigned)Ww) return;
    int cell = (b * Ww + y) * Hh + x;
    int slot = atomicAdd(&g_fill[cell], 1);
    g_pts[slot] = p;
}

// ======== fp16 2-term m16n8k16 GEMM: CSR gather-sum -> MMA -> fused scatter ========
// smem map (bytes): f16x2 tiles, 64 words per row (=128 halves)
#define SM_AHI 0                     // 64x64w   16384
#define SM_ALO 16384                 //          16384
#define SM_BHI 32768                 // 256x64w  65536
#define SM_CL  98304                 // 64 int
#define SM_ST  98560
#define SM_CT  98816
#define SM_RS  99072
#define SM_MB  99328
#define SM_GW  99584                 // 256 f
#define SM_B2  100608                // 256 f
#define SMEM_TOTAL 101632

__global__ void __launch_bounds__(256, 2) k_gemm_mma(const float* __restrict__ feats,
                                                     float* __restrict__ out) {
    extern __shared__ char sm[];
    uint32_t* AhW = (uint32_t*)(sm + SM_AHI);
    uint32_t* AlW = (uint32_t*)(sm + SM_ALO);
    uint32_t* BhW = (uint32_t*)(sm + SM_BHI);
    int*   sCl = (int*)(sm + SM_CL);
    int*   sSt = (int*)(sm + SM_ST);
    int*   sCt = (int*)(sm + SM_CT);
    float* sRs = (float*)(sm + SM_RS);
    float* sMb = (float*)(sm + SM_MB);
    float* sGw = (float*)(sm + SM_GW);
    float* sB2 = (float*)(sm + SM_B2);

    int t = threadIdx.x;
    int lane = t & 31, wid = t >> 5;
    int grp = lane >> 2, tg = lane & 3;
    int warp_m = wid >> 2;            // 0..1
    int warp_n = wid & 3;             // 0..3
    int mbase = warp_m * 32;
    int nbase = warp_n * 64;

    // ---- load B: fp16 hi only, swizzled [n][k] ----
    for (int i = t; i < 256 * 32; i += 256) {
        int n = i >> 5, f4 = i & 31;
        float4 v = ((const float4*)g_W2)[i];
        uint32_t h0 = pack_h2(v.x, v.y);
        uint32_t h1 = pack_h2(v.z, v.w);
        int s0 = swb(n, 2 * f4);
        BhW[s0] = h0; BhW[s0 + 1] = h1;
    }
    for (int i = t; i < COUT; i += 256) { sGw[i] = g_gw[i]; sB2[i] = g_bias2[i]; }

    int ncell  = g_ncells;
    int ntiles = (ncell + TILE_M - 1) / TILE_M;

    // A builder mapping: cell m = t>>2, quarter q = t&3
    int lm = t >> 2, lq = t & 3;
    int am0 = mbase + grp;

    for (int tile = blockIdx.x; tile < ntiles; tile += gridDim.x) {
        __syncthreads();
        if (t < TILE_M) {
            int ci = tile * TILE_M + t;
            int cid = (ci < ncell) ? g_celllist[ci] : -1;
            sCl[t] = cid;
            sSt[t] = (cid >= 0) ? g_start[cid] : 0;
            sCt[t] = (cid >= 0) ? g_cnt[cid]   : 0;
        }
        __syncthreads();

        // ---- A tile: CSR gather-sum + stats + fp16 hi/lo split + swizzled store ----
        {
            int st = sSt[lm], cn = sCt[lm];
            float4 a[8];
            #pragma unroll
            for (int j = 0; j < 8; j++) a[j] = make_float4(0.f, 0.f, 0.f, 0.f);
            for (int q = 0; q < cn; q++) {
                int p = g_pts[st + q];
                const float4* src = (const float4*)(feats + (size_t)p * CIN) + lq * 8;
                #pragma unroll
                for (int j = 0; j < 8; j++) {
                    float4 v = src[j];
                    a[j].x += v.x; a[j].y += v.y; a[j].z += v.z; a[j].w += v.w;
                }
            }
            float s = 0.f, ss = 0.f;
            #pragma unroll
            for (int j = 0; j < 8; j++) {
                float4 v = a[j];
                s  += v.x + v.y + v.z + v.w;
                ss += v.x*v.x + v.y*v.y + v.z*v.z + v.w*v.w;
                uint32_t h0 = pack_h2(v.x, v.y);
                uint32_t h1 = pack_h2(v.z, v.w);
                uint32_t l0 = pack_h2(v.x - h2_lo_f(h0), v.y - h2_hi_f(h0));
                uint32_t l1 = pack_h2(v.z - h2_lo_f(h1), v.w - h2_hi_f(h1));
                int s0 = swb(lm, 2 * (lq * 8 + j));
                AhW[s0] = h0; AhW[s0 + 1] = h1;
                AlW[s0] = l0; AlW[s0 + 1] = l1;
            }
            s  += __shfl_xor_sync(0xFFFFFFFFu, s,  1);
            ss += __shfl_xor_sync(0xFFFFFFFFu, ss, 1);
            s  += __shfl_xor_sync(0xFFFFFFFFu, s,  2);
            ss += __shfl_xor_sync(0xFFFFFFFFu, ss, 2);
            if (lq == 0) {
                float mu  = s * (1.f / CIN);
                float var = ss * (1.f / CIN) - mu * mu;
                float rs  = rsqrtf(var + EPSf);
                sRs[lm] = rs;
                sMb[lm] = -rs * mu;
            }
        }
        __syncthreads();

        // ---- mainloop: 8 k16-steps, 2-term fp16 (AhBh + AlBh) ----
        float acc[2][8][4];
        #pragma unroll
        for (int a = 0; a < 2; a++)
            #pragma unroll
            for (int b = 0; b < 8; b++)
                #pragma unroll
                for (int c = 0; c < 4; c++) acc[a][b][c] = 0.f;

        #pragma unroll
        for (int ks = 0; ks < 8; ks++) {
            int w0 = 8 * ks + tg;
            int w1 = w0 + 4;
            uint32_t ah[2][4], al[2][4];
            #pragma unroll
            for (int mf = 0; mf < 2; mf++) {
                int r0 = am0 + mf * 16, r1 = r0 + 8;
                ah[mf][0] = AhW[swb(r0, w0)];
                ah[mf][1] = AhW[swb(r1, w0)];
                ah[mf][2] = AhW[swb(r0, w1)];
                ah[mf][3] = AhW[swb(r1, w1)];
                al[mf][0] = AlW[swb(r0, w0)];
                al[mf][1] = AlW[swb(r1, w0)];
                al[mf][2] = AlW[swb(r0, w1)];
                al[mf][3] = AlW[swb(r1, w1)];
            }
            #pragma unroll
            for (int nf = 0; nf < 8; nf++) {
                int n0 = nbase + nf * 8 + grp;
                uint32_t bh[2];
                bh[0] = BhW[swb(n0, w0)];
                bh[1] = BhW[swb(n0, w1)];
                mma16(acc[0][nf], ah[0], bh);
                mma16(acc[1][nf], ah[1], bh);
                mma16(acc[0][nf], al[0], bh);
                mma16(acc[1][nf], al[1], bh);
            }
        }

        // ---- epilogue: affine, then write directly to every owning point ----
        #pragma unroll
        for (int mf = 0; mf < 2; mf++) {
            #pragma unroll
            for (int rr = 0; rr < 2; rr++) {
                int r = am0 + mf * 16 + rr * 8;
                int cid = sCl[r];
                if (cid < 0) continue;
                float rs = sRs[r], mb = sMb[r];
                float2 res[8];
                #pragma unroll
                for (int nf = 0; nf < 8; nf++) {
                    int n0 = nbase + nf * 8 + 2 * tg;
                    res[nf].x = rs * acc[mf][nf][rr * 2 + 0] + mb * sGw[n0]     + sB2[n0];
                    res[nf].y = rs * acc[mf][nf][rr * 2 + 1] + mb * sGw[n0 + 1] + sB2[n0 + 1];
                }
                int st = sSt[r], cn = sCt[r];
                for (int q = 0; q < cn; q++) {
                    int p = g_pts[st + q];
                    float* bp = out + (size_t)p * COUT + nbase + 2 * tg;
                    #pragma unroll
                    for (int nf = 0; nf < 8; nf++)
                        *(float2*)(bp + nf * 8) = res[nf];
                }
            }
        }
    }
}

__global__ void k_idx(const int* __restrict__ idx, float* __restrict__ out, int n) {
    int g = blockIdx.x * blockDim.x + threadIdx.x;
    if (g < n) out[g] = (float)idx[g];
}

extern "C" void kernel_launch(void* const* d_in, const int* in_sizes, int n_in,
                              void* d_out, int out_size) {
    const float* feats = (const float*)d_in[0];
    const int*   idx   = (const int*)d_in[1];
    const float* gamma = (const float*)d_in[2];
    const float* beta  = (const float*)d_in[3];
    const float* lw    = (const float*)d_in[4];
    float* out = (float*)d_out;

    cudaFuncSetAttribute(k_gemm_mma, cudaFuncAttributeMaxDynamicSharedMemorySize, SMEM_TOTAL);

    k_init<<<550, 256>>>();
    k_prep<<<COUT, CIN>>>(lw, gamma, beta);
    k_count<<<(NPTS * 32) / 256, 256>>>(idx, out);
    k_compact<<<(NCELL + 255) / 256, 256>>>();
    k_fill<<<(NPTS + 255) / 256, 256>>>(idx);
    k_gemm_mma<<<296, 256, SMEM_TOTAL>>>(feats, out);

    long long tail = (long long)out_size - (long long)NPTS * COUT;
    if (tail > 0) {
        int n = (int)((tail < (long long)NPTS * 3) ? tail : (long long)NPTS * 3);
        k_idx<<<(n + 255) / 256, 256>>>(idx, out + (size_t)NPTS * COUT, n);
    }
}

// round 17
// speedup vs baseline: 3.0374x; 1.1446x over previous
#include <cuda_runtime.h>
#include <cuda_fp16.h>
#include <cstdint>

#define Bb   4
#define Hh   176
#define Ww   200
#define CIN  128
#define COUT 256
#define NPTS (4096*64)
#define NCELL (Bb*Ww*Hh)
#define EPSf 1e-5f

#define TILE_M 64           // cells per GEMM tile

// -------- scratch (device globals; no allocation allowed) --------
__device__ int   g_cnt[NCELL];                      // points per cell
__device__ int   g_start[NCELL];                    // CSR segment base
__device__ int   g_fill[NCELL];                     // CSR fill cursor
__device__ int   g_pts[NPTS];                       // CSR point ids
__device__ int   g_celllist[NCELL];
__device__ int   g_ncells;
__device__ int   g_nptstotal;
__device__ float g_W2[COUT*CIN];                    // W*gamma (full fp32), [o][c]
__device__ float g_gw[COUT];                        // sum_c W2[o,c]
__device__ float g_bias2[COUT];                     // sum_c beta[c]*W[o,c]

// ======================= helpers =======================
__device__ __forceinline__ uint32_t pack_h2(float a0, float a1) {
    __half2 h = __halves2half2(__float2half_rn(a0), __float2half_rn(a1));
    return *(uint32_t*)&h;
}
__device__ __forceinline__ uint32_t smem_u32(const void* p) {
    uint32_t a;
    asm("{ .reg .u64 t; cvta.to.shared.u64 t, %1; cvt.u32.u64 %0, t; }" : "=r"(a) : "l"(p));
    return a;
}

// m16n8k16 fp16 MMA, f32 accum
__device__ __forceinline__ void mma16(float* c, const uint32_t* a, const uint32_t* b) {
    asm volatile(
        "mma.sync.aligned.m16n8k16.row.col.f32.f16.f16.f32 "
        "{%0,%1,%2,%3}, {%4,%5,%6,%7}, {%8,%9}, {%0,%1,%2,%3};"
        : "+f"(c[0]), "+f"(c[1]), "+f"(c[2]), "+f"(c[3])
        : "r"(a[0]), "r"(a[1]), "r"(a[2]), "r"(a[3]), "r"(b[0]), "r"(b[1]));
}

__device__ __forceinline__ void ldsm4(uint32_t* r, uint32_t addr) {
    asm volatile("ldmatrix.sync.aligned.m8n8.x4.shared.b16 {%0,%1,%2,%3}, [%4];"
        : "=r"(r[0]), "=r"(r[1]), "=r"(r[2]), "=r"(r[3]) : "r"(addr));
}

// swizzled WORD index in a row-major [rows][64-word] f16x2 tile (row = 128 halves)
__device__ __forceinline__ int swb(int r, int w) {
    return (r * 16 + ((w >> 2) ^ (r & 7))) * 4 + (w & 3);
}

// ======================= small kernels =======================
__global__ void k_init() {
    int i = blockIdx.x * blockDim.x + threadIdx.x;
    int stride = gridDim.x * blockDim.x;
    for (int j = i; j < NCELL; j += stride) {
        g_cnt[j] = 0;
        g_start[j] = 0;
        g_fill[j] = 0;
    }
    if (i == 0) { g_ncells = 0; g_nptstotal = 0; }
}

__global__ void k_prep(const float* __restrict__ lw,
                       const float* __restrict__ gamma,
                       const float* __restrict__ beta) {
    int o = blockIdx.x;
    int c = threadIdx.x;
    float w  = lw[o * CIN + c];
    float w2 = w * gamma[c];
    g_W2[o * CIN + c] = w2;
    float gwv = w2;
    float b2  = w * beta[c];
    for (int s = 16; s > 0; s >>= 1) {
        gwv += __shfl_xor_sync(0xFFFFFFFFu, gwv, s);
        b2  += __shfl_xor_sync(0xFFFFFFFFu, b2,  s);
    }
    __shared__ float sg[4], sb[4];
    if ((c & 31) == 0) { sg[c >> 5] = gwv; sb[c >> 5] = b2; }
    __syncthreads();
    if (c == 0) {
        g_gw[o]    = sg[0] + sg[1] + sg[2] + sg[3];
        g_bias2[o] = sb[0] + sb[1] + sb[2] + sb[3];
    }
}

// count points per cell (1 warp/point); invalid points zero their output row
__global__ void k_count(const int* __restrict__ idx, float* __restrict__ out) {
    int g = blockIdx.x * blockDim.x + threadIdx.x;
    int p = g >> 5;
    int l = g & 31;
    if (p >= NPTS) return;
    int cell = -1;
    if (l == 0) {
        int b = idx[3 * p + 0];
        int x = idx[3 * p + 1];
        int y = idx[3 * p + 2];
        if ((unsigned)x < (unsigned)Hh && (unsigned)y < (unsigned)Ww)
            cell = (b * Ww + y) * Hh + x;
    }
    cell = __shfl_sync(0xFFFFFFFFu, cell, 0);
    if (cell < 0) {
        float4 z = make_float4(0.f, 0.f, 0.f, 0.f);
        float4* o4 = (float4*)(out + (size_t)p * COUT);
        o4[2 * l]     = z;
        o4[2 * l + 1] = z;
        return;
    }
    if (l == 0) atomicAdd(&g_cnt[cell], 1);
}

// compact occupied cells + CSR segments; warp-aggregated atomics
__global__ void k_compact() {
    int c = blockIdx.x * blockDim.x + threadIdx.x;
    int lane = threadIdx.x & 31;
    bool occ = (c < NCELL) && (g_cnt[c] > 0);
    int cnt = occ ? g_cnt[c] : 0;
    unsigned m = __ballot_sync(0xFFFFFFFFu, occ);
    int scan = cnt;
    #pragma unroll
    for (int d = 1; d < 32; d <<= 1) {
        int v = __shfl_up_sync(0xFFFFFFFFu, scan, d);
        if (lane >= d) scan += v;
    }
    int total = __shfl_sync(0xFFFFFFFFu, scan, 31);
    int excl  = scan - cnt;
    int nOcc  = __popc(m);
    int rank  = __popc(m & ((1u << lane) - 1));
    int b1 = 0, b2 = 0;
    if (lane == 0 && nOcc > 0) {
        b1 = atomicAdd(&g_ncells, nOcc);
        b2 = atomicAdd(&g_nptstotal, total);
    }
    b1 = __shfl_sync(0xFFFFFFFFu, b1, 0);
    b2 = __shfl_sync(0xFFFFFFFFu, b2, 0);
    if (occ) {
        g_celllist[b1 + rank] = c;
        g_start[c] = b2 + excl;
        g_fill[c]  = b2 + excl;
    }
}

// CSR fill: record which points own each cell
__global__ void k_fill(const int* __restrict__ idx) {
    int p = blockIdx.x * blockDim.x + threadIdx.x;
    if (p >= NPTS) return;
    int b = idx[3 * p + 0];
    int x = idx[3 * p + 1];
    int y = idx[3 * p + 2];
    if ((unsigned)x >= (unsigned)Hh || (unsigned)y >= (unsigned)Ww) return;
    int cell = (b * Ww + y) * Hh + x;
    int slot = atomicAdd(&g_fill[cell], 1);
    g_pts[slot] = p;
}

// ======== fp16 single-term m16n8k16 GEMM + ldmatrix: CSR gather -> MMA -> fused scatter ========
// smem map (bytes): f16x2 tiles, 64 words per row (=128 halves = 256B)
#define SM_AHI 0                     // 64x64w   16384
#define SM_BHI 16384                 // 256x64w  65536
#define SM_CL  81920                 // 64 int
#define SM_ST  82176
#define SM_CT  82432
#define SM_RS  82688
#define SM_MB  82944
#define SM_GW  83200                 // 256 f
#define SM_B2  84224                 // 256 f
#define SMEM_TOTAL 85248

__global__ void __launch_bounds__(256, 2) k_gemm_mma(const float* __restrict__ feats,
                                                     float* __restrict__ out) {
    extern __shared__ char sm[];
    uint32_t* AhW = (uint32_t*)(sm + SM_AHI);
    uint32_t* BhW = (uint32_t*)(sm + SM_BHI);
    int*   sCl = (int*)(sm + SM_CL);
    int*   sSt = (int*)(sm + SM_ST);
    int*   sCt = (int*)(sm + SM_CT);
    float* sRs = (float*)(sm + SM_RS);
    float* sMb = (float*)(sm + SM_MB);
    float* sGw = (float*)(sm + SM_GW);
    float* sB2 = (float*)(sm + SM_B2);

    int t = threadIdx.x;
    int lane = t & 31, wid = t >> 5;
    int grp = lane >> 2, tg = lane & 3;
    int warp_m = wid >> 2;            // 0..1
    int warp_n = wid & 3;             // 0..3
    int mbase = warp_m * 32;
    int nbase = warp_n * 64;

    uint32_t smb = smem_u32(sm);

    // ldmatrix per-lane addressing (row stride = 256 B)
    int gl = lane >> 3;
    int aRow0 = mbase + (gl & 1) * 8 + (lane & 7);
    uint32_t paA0 = smb + SM_AHI + (uint32_t)aRow0 * 256;
    uint32_t paA1 = paA0 + 16 * 256;
    int aXor = aRow0 & 7, aBit = gl >> 1;
    int bRow = nbase + (gl >> 1) * 8 + (lane & 7);
    uint32_t paB = smb + SM_BHI + (uint32_t)bRow * 256;
    int bXor = bRow & 7, bBit = gl & 1;

    // ---- load B: fp16, swizzled [n][k] ----
    for (int i = t; i < 256 * 32; i += 256) {
        int n = i >> 5, f4 = i & 31;
        float4 v = ((const float4*)g_W2)[i];
        uint32_t h0 = pack_h2(v.x, v.y);
        uint32_t h1 = pack_h2(v.z, v.w);
        int s0 = swb(n, 2 * f4);
        BhW[s0] = h0; BhW[s0 + 1] = h1;
    }
    for (int i = t; i < COUT; i += 256) { sGw[i] = g_gw[i]; sB2[i] = g_bias2[i]; }

    int ncell  = g_ncells;
    int ntiles = (ncell + TILE_M - 1) / TILE_M;

    // A builder mapping: cell m = t>>2, quarter q = t&3
    int lm = t >> 2, lq = t & 3;
    int am0 = mbase + grp;

    for (int tile = blockIdx.x; tile < ntiles; tile += gridDim.x) {
        __syncthreads();
        if (t < TILE_M) {
            int ci = tile * TILE_M + t;
            int cid = (ci < ncell) ? g_celllist[ci] : -1;
            sCl[t] = cid;
            sSt[t] = (cid >= 0) ? g_start[cid] : 0;
            sCt[t] = (cid >= 0) ? g_cnt[cid]   : 0;
        }
        __syncthreads();

        // ---- A tile: CSR gather-sum + stats + fp16 pack + swizzled store ----
        {
            int st = sSt[lm], cn = sCt[lm];
            float4 a[8];
            #pragma unroll
            for (int j = 0; j < 8; j++) a[j] = make_float4(0.f, 0.f, 0.f, 0.f);
            for (int q = 0; q < cn; q++) {
                int p = g_pts[st + q];
                const float4* src = (const float4*)(feats + (size_t)p * CIN) + lq * 8;
                #pragma unroll
                for (int j = 0; j < 8; j++) {
                    float4 v = src[j];
                    a[j].x += v.x; a[j].y += v.y; a[j].z += v.z; a[j].w += v.w;
                }
            }
            float s = 0.f, ss = 0.f;
            #pragma unroll
            for (int j = 0; j < 8; j++) {
                float4 v = a[j];
                s  += v.x + v.y + v.z + v.w;
                ss += v.x*v.x + v.y*v.y + v.z*v.z + v.w*v.w;
                uint32_t h0 = pack_h2(v.x, v.y);
                uint32_t h1 = pack_h2(v.z, v.w);
                int s0 = swb(lm, 2 * (lq * 8 + j));
                AhW[s0] = h0; AhW[s0 + 1] = h1;
            }
            s  += __shfl_xor_sync(0xFFFFFFFFu, s,  1);
            ss += __shfl_xor_sync(0xFFFFFFFFu, ss, 1);
            s  += __shfl_xor_sync(0xFFFFFFFFu, s,  2);
            ss += __shfl_xor_sync(0xFFFFFFFFu, ss, 2);
            if (lq == 0) {
                float mu  = s * (1.f / CIN);
                float var = ss * (1.f / CIN) - mu * mu;
                float rs  = rsqrtf(var + EPSf);
                sRs[lm] = rs;
                sMb[lm] = -rs * mu;
            }
        }
        __syncthreads();

        // ---- mainloop: 8 k16-steps, single-term fp16, ldmatrix operands ----
        float acc[2][8][4];
        #pragma unroll
        for (int a = 0; a < 2; a++)
            #pragma unroll
            for (int b = 0; b < 8; b++)
                #pragma unroll
                for (int c = 0; c < 4; c++) acc[a][b][c] = 0.f;

        #pragma unroll
        for (int ks = 0; ks < 8; ks++) {
            uint32_t offA = (uint32_t)(((2 * ks + aBit) ^ aXor) << 4);
            uint32_t offB = (uint32_t)(((2 * ks + bBit) ^ bXor) << 4);
            uint32_t ah0[4], ah1[4];
            ldsm4(ah0, paA0 + offA);
            ldsm4(ah1, paA1 + offA);
            uint32_t bfr[4][4];
            ldsm4(bfr[0], paB + offB);
            ldsm4(bfr[1], paB + 16 * 256 + offB);
            ldsm4(bfr[2], paB + 32 * 256 + offB);
            ldsm4(bfr[3], paB + 48 * 256 + offB);
            #pragma unroll
            for (int j = 0; j < 4; j++) {
                mma16(acc[0][2 * j],     ah0, &bfr[j][0]);
                mma16(acc[1][2 * j],     ah1, &bfr[j][0]);
                mma16(acc[0][2 * j + 1], ah0, &bfr[j][2]);
                mma16(acc[1][2 * j + 1], ah1, &bfr[j][2]);
            }
        }

        // ---- epilogue: affine, then write directly to every owning point ----
        #pragma unroll
        for (int mf = 0; mf < 2; mf++) {
            #pragma unroll
            for (int rr = 0; rr < 2; rr++) {
                int r = am0 + mf * 16 + rr * 8;
                int cid = sCl[r];
                if (cid < 0) continue;
                float rs = sRs[r], mb = sMb[r];
                float2 res[8];
                #pragma unroll
                for (int nf = 0; nf < 8; nf++) {
                    int n0 = nbase + nf * 8 + 2 * tg;
                    res[nf].x = rs * acc[mf][nf][rr * 2 + 0] + mb * sGw[n0]     + sB2[n0];
                    res[nf].y = rs * acc[mf][nf][rr * 2 + 1] + mb * sGw[n0 + 1] + sB2[n0 + 1];
                }
                int st = sSt[r], cn = sCt[r];
                for (int q = 0; q < cn; q++) {
                    int p = g_pts[st + q];
                    float* bp = out + (size_t)p * COUT + nbase + 2 * tg;
                    #pragma unroll
                    for (int nf = 0; nf < 8; nf++)
                        *(float2*)(bp + nf * 8) = res[nf];
                }
            }
        }
    }
}

__global__ void k_idx(const int* __restrict__ idx, float* __restrict__ out, int n) {
    int g = blockIdx.x * blockDim.x + threadIdx.x;
    if (g < n) out[g] = (float)idx[g];
}

extern "C" void kernel_launch(void* const* d_in, const int* in_sizes, int n_in,
                              void* d_out, int out_size) {
    const float* feats = (const float*)d_in[0];
    const int*   idx   = (const int*)d_in[1];
    const float* gamma = (const float*)d_in[2];
    const float* beta  = (const float*)d_in[3];
    const float* lw    = (const float*)d_in[4];
    float* out = (float*)d_out;

    cudaFuncSetAttribute(k_gemm_mma, cudaFuncAttributeMaxDynamicSharedMemorySize, SMEM_TOTAL);

    k_init<<<550, 256>>>();
    k_prep<<<COUT, CIN>>>(lw, gamma, beta);
    k_count<<<(NPTS * 32) / 256, 256>>>(idx, out);
    k_compact<<<(NCELL + 255) / 256, 256>>>();
    k_fill<<<(NPTS + 255) / 256, 256>>>(idx);
    k_gemm_mma<<<296, 256, SMEM_TOTAL>>>(feats, out);

    long long tail = (long long)out_size - (long long)NPTS * COUT;
    if (tail > 0) {
        int n = (int)((tail < (long long)NPTS * 3) ? tail : (long long)NPTS * 3);
        k_idx<<<(n + 255) / 256, 256>>>(idx, out + (size_t)NPTS * COUT, n);
    }
}